// round 7
// baseline (speedup 1.0000x reference)
#include <cuda_runtime.h>
#include <cuda_bf16.h>
#include <cstdint>

#define HD 128
#define WPB 8                       // warps per CTA
#define NTHREADS (WPB * 32)
#define GRID1 592                   // 148 SMs * 4 CTAs -> exactly one co-resident wave
#define NWTOT (GRID1 * WPB)         // 4736 worker warps
#define BMAX 2048                   // scratch sized for up to 2048 segments

// ---- persistent scratch (zero-initialized at module load) ----
// Invariant: for an EMPTY segment s nothing ever writes g_seg_end[s] (any run,
// any replay) so it stays 0; a NON-EMPTY segment gets g_seg_end[s]=j>=1 from
// exactly one warp. Barrier counters are reset to 0 by the last departing CTA
// each run, so every graph replay starts from a clean state.
__device__ float g_head_num[NWTOT * HD];
__device__ float g_tail_num[NWTOT * HD];
__device__ float g_head_d[NWTOT];
__device__ float g_tail_d[NWTOT];
__device__ int   g_head_seg[NWTOT];
__device__ int   g_tail_seg[NWTOT];
__device__ float g_num_acc[BMAX * HD];   // direct-stored exclusive segments
__device__ float g_d_acc[BMAX];
__device__ int   g_seg_start[BMAX];
__device__ int   g_seg_end[BMAX];        // 0 => empty segment
__device__ int   g_arrive;               // grid-barrier arrival ticket
__device__ int   g_depart;               // grid-barrier departure ticket

// Fused kernel: phase 1 streams x once (one contiguous run of rows per warp,
// 4 independent LDG.128 per lane per iter); software grid barrier; phase 2
// (epilogue) gathers head/tail partials and writes the output — all in one
// launch, so the old K2's 8us launch executes inside the tail-imbalance
// window of phase 1.
__global__ void __launch_bounds__(NTHREADS, 4)
gap_fused(const float* __restrict__ x,
          const int*   __restrict__ batch,
          const float* __restrict__ W,
          float*       __restrict__ out,
          int N, int B)
{
    const int wid  = threadIdx.x >> 5;
    const int lane = threadIdx.x & 31;
    const int g    = blockIdx.x * WPB + wid;

    const int rpw = (N + NWTOT - 1) / NWTOT;
    const long long rl = (long long)g * rpw;

    int hseg = -1, tseg = -1;

    // ---------------- phase 1: stream x ----------------
    if (rl < N) {
        const int lo = (int)rl;
        const int hi = min(lo + rpw, N);
        const float4 Wv = *reinterpret_cast<const float4*>(W + lane * 4);
        const long long col = (long long)lane * 4;

        int i = lo;
        while (i < hi) {
            const int seg = batch[i];
            // upper_bound(seg) in (i, hi)
            int a = i + 1, b = hi;
            while (a < b) { int m = (a + b) >> 1; if (batch[m] <= seg) a = m + 1; else b = m; }
            const int j = a;

            float  d = 0.0f;
            float4 num = make_float4(0.0f, 0.0f, 0.0f, 0.0f);

            int r = i;
            for (; r + 4 <= j; r += 4) {
                const float4 x0 = __ldcs(reinterpret_cast<const float4*>(x + (long long)(r    ) * HD + col));
                const float4 x1 = __ldcs(reinterpret_cast<const float4*>(x + (long long)(r + 1) * HD + col));
                const float4 x2 = __ldcs(reinterpret_cast<const float4*>(x + (long long)(r + 2) * HD + col));
                const float4 x3 = __ldcs(reinterpret_cast<const float4*>(x + (long long)(r + 3) * HD + col));

                float p0 = x0.x * Wv.x + x0.y * Wv.y + x0.z * Wv.z + x0.w * Wv.w;
                float p1 = x1.x * Wv.x + x1.y * Wv.y + x1.z * Wv.z + x1.w * Wv.w;
                float p2 = x2.x * Wv.x + x2.y * Wv.y + x2.z * Wv.z + x2.w * Wv.w;
                float p3 = x3.x * Wv.x + x3.y * Wv.y + x3.z * Wv.z + x3.w * Wv.w;
                #pragma unroll
                for (int o = 16; o > 0; o >>= 1) {
                    p0 += __shfl_xor_sync(0xffffffffu, p0, o);
                    p1 += __shfl_xor_sync(0xffffffffu, p1, o);
                    p2 += __shfl_xor_sync(0xffffffffu, p2, o);
                    p3 += __shfl_xor_sync(0xffffffffu, p3, o);
                }
                const float e0 = __expf(p0);
                const float e1 = __expf(p1);
                const float e2 = __expf(p2);
                const float e3 = __expf(p3);
                d += (e0 + e1) + (e2 + e3);
                num.x += e0 * x0.x + e1 * x1.x + e2 * x2.x + e3 * x3.x;
                num.y += e0 * x0.y + e1 * x1.y + e2 * x2.y + e3 * x3.y;
                num.z += e0 * x0.z + e1 * x1.z + e2 * x2.z + e3 * x3.z;
                num.w += e0 * x0.w + e1 * x1.w + e2 * x2.w + e3 * x3.w;
            }
            for (; r < j; r++) {
                const float4 xv = __ldcs(reinterpret_cast<const float4*>(x + (long long)r * HD + col));
                float p = xv.x * Wv.x + xv.y * Wv.y + xv.z * Wv.z + xv.w * Wv.w;
                #pragma unroll
                for (int o = 16; o > 0; o >>= 1) p += __shfl_xor_sync(0xffffffffu, p, o);
                const float e = __expf(p);
                d += e;
                num.x += e * xv.x; num.y += e * xv.y; num.z += e * xv.z; num.w += e * xv.w;
            }

            const bool sb = (i == lo) && (lo > 0) && (batch[lo - 1] == seg);   // continues before
            const bool ea = (j == hi) && (hi < N) && (batch[hi] == seg);       // continues after

            if (lane == 0) {
                if (!sb) g_seg_start[seg] = i;
                if (!ea) g_seg_end[seg]   = j;   // j >= 1
            }

            if (!sb && !ea) {
                *reinterpret_cast<float4*>(g_num_acc + (long long)seg * HD + lane * 4) = num;
                if (lane == 0) g_d_acc[seg] = d;
            } else if (sb) {
                hseg = seg;
                *reinterpret_cast<float4*>(g_head_num + (long long)g * HD + lane * 4) = num;
                if (lane == 0) g_head_d[g] = d;
            } else {
                tseg = seg;
                *reinterpret_cast<float4*>(g_tail_num + (long long)g * HD + lane * 4) = num;
                if (lane == 0) g_tail_d[g] = d;
            }
            i = j;
        }
    }
    if (lane == 0) { g_head_seg[g] = hseg; g_tail_seg[g] = tseg; }

    // ---------------- software grid barrier ----------------
    __syncthreads();
    __threadfence();                        // release all phase-1 stores
    if (threadIdx.x == 0) {
        atomicAdd(&g_arrive, 1);
        while (*(volatile int*)&g_arrive < GRID1) __nanosleep(128);
    }
    __syncthreads();
    __threadfence();                        // acquire other CTAs' stores

    // ---------------- phase 2: epilogue (old K2) ----------------
    // CTA handles segments blockIdx.x, blockIdx.x+GRID1, ... using threads 0-127.
    const int t = threadIdx.x;
    if (t < HD) {
        for (int s = blockIdx.x; s < B; s += GRID1) {
            const int se = g_seg_end[s];
            if (se == 0) { out[(long long)s * HD + t] = 0.0f; continue; }
            const int ss = g_seg_start[s];

            const int glo = ss / rpw;
            const int ghi = (se - 1) / rpw;

            float num = 0.0f, d = 0.0f;
            int matches = 0;
            for (int gg = glo; gg <= ghi; gg++) {
                if (g_head_seg[gg] == s) { num += g_head_num[(long long)gg * HD + t]; d += g_head_d[gg]; matches++; }
                if (g_tail_seg[gg] == s) { num += g_tail_num[(long long)gg * HD + t]; d += g_tail_d[gg]; matches++; }
            }
            if (matches == 0) {
                num = g_num_acc[(long long)s * HD + t];
                d   = g_d_acc[s];
            }
            out[(long long)s * HD + t] = num / (d + 1e-16f);
        }
    }

    // ---------------- barrier reset for the next replay ----------------
    __syncthreads();
    if (threadIdx.x == 0) {
        const int old = atomicAdd(&g_depart, 1);
        if (old == GRID1 - 1) {             // last departing CTA cleans up
            g_arrive = 0;
            g_depart = 0;
            __threadfence();
        }
    }
}

extern "C" void kernel_launch(void* const* d_in, const int* in_sizes, int n_in,
                              void* d_out, int out_size)
{
    const float* x     = (const float*)d_in[0];
    // d_in[1] = edge_index (unused by the forward math)
    const int*   batch = (const int*)d_in[2];
    const float* W     = (const float*)d_in[3];
    // d_in[4] = b (zeros; cancels in the softmax)
    float* out = (float*)d_out;

    const int N = in_sizes[2];
    const int B = out_size / HD;

    gap_fused<<<GRID1, NTHREADS>>>(x, batch, W, out, N, B);
}

// round 8
// speedup vs baseline: 1.0028x; 1.0028x over previous
#include <cuda_runtime.h>
#include <cuda_bf16.h>
#include <cstdint>

#define HD 128
#define WPB 8                       // warps per CTA
#define NTHREADS (WPB * 32)
#define GRID1 592                   // 148 SMs * 4 CTAs; at 5 CTAs/SM capacity 740 -> all co-resident
#define NWTOT (GRID1 * WPB)         // 4736 worker warps
#define BMAX 2048                   // scratch sized for up to 2048 segments

// ---- persistent scratch (zero-initialized at module load) ----
// Invariant: for an EMPTY segment s nothing ever writes g_seg_end[s] (any run,
// any replay) so it stays 0; a NON-EMPTY segment gets g_seg_end[s]=j>=1 from
// exactly one warp. Barrier counters reset to 0 by the last departing CTA.
__device__ float g_head_num[NWTOT * HD];
__device__ float g_tail_num[NWTOT * HD];
__device__ float g_head_d[NWTOT];
__device__ float g_tail_d[NWTOT];
__device__ int   g_head_seg[NWTOT];
__device__ int   g_tail_seg[NWTOT];
__device__ float g_num_acc[BMAX * HD];   // direct-stored exclusive segments
__device__ float g_d_acc[BMAX];
__device__ int   g_seg_start[BMAX];
__device__ int   g_seg_end[BMAX];        // 0 => empty segment
__device__ int   g_arrive;               // grid-barrier arrival ticket
__device__ int   g_depart;               // grid-barrier departure ticket

// Fused: phase 1 streams x once (contiguous rows per warp, 4 independent
// LDG.128/lane/iter); software grid barrier; phase 2 gathers partials and
// writes out. Reg cap 51 (launch_bounds min 5 CTAs/SM) keeps 40 warps/SM for
// phase-1 latency hiding — the R7 regression was regs=64 -> 32 warps.
__global__ void __launch_bounds__(NTHREADS, 5)
gap_fused(const float* __restrict__ x,
          const int*   __restrict__ batch,
          const float* __restrict__ W,
          float*       __restrict__ out,
          int N, int B)
{
    const int wid  = threadIdx.x >> 5;
    const int lane = threadIdx.x & 31;
    const int g    = blockIdx.x * WPB + wid;

    const int rpw = (N + NWTOT - 1) / NWTOT;
    const long long rl = (long long)g * rpw;

    int hseg = -1, tseg = -1;

    // ---------------- phase 1: stream x ----------------
    if (rl < N) {
        const int lo = (int)rl;
        const int hi = min(lo + rpw, N);
        const float4 Wv = *reinterpret_cast<const float4*>(W + lane * 4);
        const long long col = (long long)lane * 4;

        int i = lo;
        while (i < hi) {
            const int seg = batch[i];
            // upper_bound(seg) in (i, hi)
            int a = i + 1, b = hi;
            while (a < b) { int m = (a + b) >> 1; if (batch[m] <= seg) a = m + 1; else b = m; }
            const int j = a;

            float  d = 0.0f;
            float4 num = make_float4(0.0f, 0.0f, 0.0f, 0.0f);

            int r = i;
            for (; r + 4 <= j; r += 4) {
                const float4 x0 = __ldcs(reinterpret_cast<const float4*>(x + (long long)(r    ) * HD + col));
                const float4 x1 = __ldcs(reinterpret_cast<const float4*>(x + (long long)(r + 1) * HD + col));
                const float4 x2 = __ldcs(reinterpret_cast<const float4*>(x + (long long)(r + 2) * HD + col));
                const float4 x3 = __ldcs(reinterpret_cast<const float4*>(x + (long long)(r + 3) * HD + col));

                float p0 = x0.x * Wv.x + x0.y * Wv.y + x0.z * Wv.z + x0.w * Wv.w;
                float p1 = x1.x * Wv.x + x1.y * Wv.y + x1.z * Wv.z + x1.w * Wv.w;
                float p2 = x2.x * Wv.x + x2.y * Wv.y + x2.z * Wv.z + x2.w * Wv.w;
                float p3 = x3.x * Wv.x + x3.y * Wv.y + x3.z * Wv.z + x3.w * Wv.w;
                #pragma unroll
                for (int o = 16; o > 0; o >>= 1) {
                    p0 += __shfl_xor_sync(0xffffffffu, p0, o);
                    p1 += __shfl_xor_sync(0xffffffffu, p1, o);
                    p2 += __shfl_xor_sync(0xffffffffu, p2, o);
                    p3 += __shfl_xor_sync(0xffffffffu, p3, o);
                }
                const float e0 = __expf(p0);
                const float e1 = __expf(p1);
                const float e2 = __expf(p2);
                const float e3 = __expf(p3);
                d += (e0 + e1) + (e2 + e3);
                num.x += e0 * x0.x + e1 * x1.x + e2 * x2.x + e3 * x3.x;
                num.y += e0 * x0.y + e1 * x1.y + e2 * x2.y + e3 * x3.y;
                num.z += e0 * x0.z + e1 * x1.z + e2 * x2.z + e3 * x3.z;
                num.w += e0 * x0.w + e1 * x1.w + e2 * x2.w + e3 * x3.w;
            }
            for (; r < j; r++) {
                const float4 xv = __ldcs(reinterpret_cast<const float4*>(x + (long long)r * HD + col));
                float p = xv.x * Wv.x + xv.y * Wv.y + xv.z * Wv.z + xv.w * Wv.w;
                #pragma unroll
                for (int o = 16; o > 0; o >>= 1) p += __shfl_xor_sync(0xffffffffu, p, o);
                const float e = __expf(p);
                d += e;
                num.x += e * xv.x; num.y += e * xv.y; num.z += e * xv.z; num.w += e * xv.w;
            }

            const bool sb = (i == lo) && (lo > 0) && (batch[lo - 1] == seg);   // continues before
            const bool ea = (j == hi) && (hi < N) && (batch[hi] == seg);       // continues after

            if (lane == 0) {
                if (!sb) g_seg_start[seg] = i;
                if (!ea) g_seg_end[seg]   = j;   // j >= 1
            }

            if (!sb && !ea) {
                *reinterpret_cast<float4*>(g_num_acc + (long long)seg * HD + lane * 4) = num;
                if (lane == 0) g_d_acc[seg] = d;
            } else if (sb) {
                hseg = seg;
                *reinterpret_cast<float4*>(g_head_num + (long long)g * HD + lane * 4) = num;
                if (lane == 0) g_head_d[g] = d;
            } else {
                tseg = seg;
                *reinterpret_cast<float4*>(g_tail_num + (long long)g * HD + lane * 4) = num;
                if (lane == 0) g_tail_d[g] = d;
            }
            i = j;
        }
    }
    if (lane == 0) { g_head_seg[g] = hseg; g_tail_seg[g] = tseg; }

    // ---------------- software grid barrier ----------------
    __syncthreads();
    __threadfence();                        // release all phase-1 stores
    if (threadIdx.x == 0) {
        atomicAdd(&g_arrive, 1);
        while (*(volatile int*)&g_arrive < GRID1) __nanosleep(64);
    }
    __syncthreads();
    __threadfence();                        // acquire other CTAs' stores

    // ---------------- phase 2: epilogue ----------------
    // All 256 threads active: half-warpgroup 0 takes segment 2*bid, half 1
    // takes 2*bid+1; 2*GRID1 = 1184 >= B so no looping in practice.
    {
        const int t    = threadIdx.x & (HD - 1);       // column 0..127
        const int half = threadIdx.x >> 7;             // 0 or 1
        for (int s = blockIdx.x * 2 + half; s < B; s += 2 * GRID1) {
            const int se = g_seg_end[s];
            if (se == 0) { out[(long long)s * HD + t] = 0.0f; continue; }
            const int ss = g_seg_start[s];

            const int glo = ss / rpw;
            const int ghi = (se - 1) / rpw;

            float num = 0.0f, d = 0.0f;
            int matches = 0;
            for (int gg = glo; gg <= ghi; gg++) {
                if (__ldcg(&g_head_seg[gg]) == s) { num += __ldcg(&g_head_num[(long long)gg * HD + t]); d += __ldcg(&g_head_d[gg]); matches++; }
                if (__ldcg(&g_tail_seg[gg]) == s) { num += __ldcg(&g_tail_num[(long long)gg * HD + t]); d += __ldcg(&g_tail_d[gg]); matches++; }
            }
            if (matches == 0) {
                num = __ldcg(&g_num_acc[(long long)s * HD + t]);
                d   = __ldcg(&g_d_acc[s]);
            }
            out[(long long)s * HD + t] = num / (d + 1e-16f);
        }
    }

    // ---------------- barrier reset for the next replay ----------------
    __syncthreads();
    if (threadIdx.x == 0) {
        const int old = atomicAdd(&g_depart, 1);
        if (old == GRID1 - 1) {             // last departing CTA cleans up
            g_arrive = 0;
            g_depart = 0;
            __threadfence();
        }
    }
}

extern "C" void kernel_launch(void* const* d_in, const int* in_sizes, int n_in,
                              void* d_out, int out_size)
{
    const float* x     = (const float*)d_in[0];
    // d_in[1] = edge_index (unused by the forward math)
    const int*   batch = (const int*)d_in[2];
    const float* W     = (const float*)d_in[3];
    // d_in[4] = b (zeros; cancels in the softmax)
    float* out = (float*)d_out;

    const int N = in_sizes[2];
    const int B = out_size / HD;

    gap_fused<<<GRID1, NTHREADS>>>(x, batch, W, out, N, B);
}

// round 9
// speedup vs baseline: 1.0450x; 1.0421x over previous
#include <cuda_runtime.h>
#include <cuda_bf16.h>
#include <cstdint>

#define HD 128
#define WPB 8                       // warps per CTA
#define NTHREADS (WPB * 32)
#define GRID1 740                   // 148 SMs * 5 CTAs (regs=48 -> 5 CTAs/SM resident)
#define NWTOT (GRID1 * WPB)         // 5920 worker warps
#define BMAX 2048                   // scratch sized for up to 2048 segments

// ---- persistent scratch (zero-initialized at module load) ----
// Invariant: for an EMPTY segment s nothing ever writes g_seg_end[s] (any run,
// any replay) so it stays 0; a NON-EMPTY segment gets g_seg_end[s]=j>=1 from
// exactly one warp. Hence g_seg_end[s]==0 <=> empty; no init kernel needed.
__device__ float g_head_num[NWTOT * HD];
__device__ float g_tail_num[NWTOT * HD];
__device__ float g_head_d[NWTOT];
__device__ float g_tail_d[NWTOT];
__device__ int   g_head_seg[NWTOT];
__device__ int   g_tail_seg[NWTOT];
__device__ float g_num_acc[BMAX * HD];   // direct-stored exclusive segments
__device__ float g_d_acc[BMAX];
__device__ int   g_seg_start[BMAX];
__device__ int   g_seg_end[BMAX];        // 0 => empty segment

// K1: each global warp g owns contiguous rows [g*RPW, min((g+1)*RPW, N)).
// Splits its range into same-segment runs; accumulates d = sum exp(s_i),
// num = sum exp(s_i)*x_i per run; flushes each run to either the exclusive
// per-segment slot or the warp's head/tail partial slot. Records the TRUE
// segment start/end rows (single writer each) so K2 needs no search.
__global__ void __launch_bounds__(NTHREADS, 5)
gap_k1(const float* __restrict__ x,
       const int*   __restrict__ batch,
       const float* __restrict__ W,
       int N)
{
    const int wid  = threadIdx.x >> 5;
    const int lane = threadIdx.x & 31;
    const int g    = blockIdx.x * WPB + wid;

    const int rpw = (N + NWTOT - 1) / NWTOT;
    const long long rl = (long long)g * rpw;

    int hseg = -1, tseg = -1;

    if (rl < N) {
        const int lo = (int)rl;
        const int hi = min(lo + rpw, N);
        const float4 Wv = *reinterpret_cast<const float4*>(W + lane * 4);
        const long long col = (long long)lane * 4;

        int i = lo;
        while (i < hi) {
            const int seg = batch[i];
            // upper_bound(seg) in (i, hi)
            int a = i + 1, b = hi;
            while (a < b) { int m = (a + b) >> 1; if (batch[m] <= seg) a = m + 1; else b = m; }
            const int j = a;

            float  d = 0.0f;
            float4 num = make_float4(0.0f, 0.0f, 0.0f, 0.0f);

            int r = i;
            // 4 consecutive rows per iter: 4 independent LDG.128, 2KB contiguous
            for (; r + 4 <= j; r += 4) {
                const float4 x0 = __ldcs(reinterpret_cast<const float4*>(x + (long long)(r    ) * HD + col));
                const float4 x1 = __ldcs(reinterpret_cast<const float4*>(x + (long long)(r + 1) * HD + col));
                const float4 x2 = __ldcs(reinterpret_cast<const float4*>(x + (long long)(r + 2) * HD + col));
                const float4 x3 = __ldcs(reinterpret_cast<const float4*>(x + (long long)(r + 3) * HD + col));

                float p0 = x0.x * Wv.x + x0.y * Wv.y + x0.z * Wv.z + x0.w * Wv.w;
                float p1 = x1.x * Wv.x + x1.y * Wv.y + x1.z * Wv.z + x1.w * Wv.w;
                float p2 = x2.x * Wv.x + x2.y * Wv.y + x2.z * Wv.z + x2.w * Wv.w;
                float p3 = x3.x * Wv.x + x3.y * Wv.y + x3.z * Wv.z + x3.w * Wv.w;
                #pragma unroll
                for (int o = 16; o > 0; o >>= 1) {
                    p0 += __shfl_xor_sync(0xffffffffu, p0, o);
                    p1 += __shfl_xor_sync(0xffffffffu, p1, o);
                    p2 += __shfl_xor_sync(0xffffffffu, p2, o);
                    p3 += __shfl_xor_sync(0xffffffffu, p3, o);
                }
                const float e0 = __expf(p0);
                const float e1 = __expf(p1);
                const float e2 = __expf(p2);
                const float e3 = __expf(p3);
                d += (e0 + e1) + (e2 + e3);
                num.x += e0 * x0.x + e1 * x1.x + e2 * x2.x + e3 * x3.x;
                num.y += e0 * x0.y + e1 * x1.y + e2 * x2.y + e3 * x3.y;
                num.z += e0 * x0.z + e1 * x1.z + e2 * x2.z + e3 * x3.z;
                num.w += e0 * x0.w + e1 * x1.w + e2 * x2.w + e3 * x3.w;
            }
            for (; r < j; r++) {
                const float4 xv = __ldcs(reinterpret_cast<const float4*>(x + (long long)r * HD + col));
                float p = xv.x * Wv.x + xv.y * Wv.y + xv.z * Wv.z + xv.w * Wv.w;
                #pragma unroll
                for (int o = 16; o > 0; o >>= 1) p += __shfl_xor_sync(0xffffffffu, p, o);
                const float e = __expf(p);
                d += e;
                num.x += e * xv.x; num.y += e * xv.y; num.z += e * xv.z; num.w += e * xv.w;
            }

            const bool sb = (i == lo) && (lo > 0) && (batch[lo - 1] == seg);   // continues before
            const bool ea = (j == hi) && (hi < N) && (batch[hi] == seg);       // continues after

            if (lane == 0) {
                if (!sb) g_seg_start[seg] = i;   // true segment start (unique writer)
                if (!ea) g_seg_end[seg]   = j;   // true segment end   (unique writer, j >= 1)
            }

            if (!sb && !ea) {
                // exclusive segment: this warp is the sole contributor
                *reinterpret_cast<float4*>(g_num_acc + (long long)seg * HD + lane * 4) = num;
                if (lane == 0) g_d_acc[seg] = d;
            } else if (sb) {
                hseg = seg;
                *reinterpret_cast<float4*>(g_head_num + (long long)g * HD + lane * 4) = num;
                if (lane == 0) g_head_d[g] = d;
            } else {
                tseg = seg;
                *reinterpret_cast<float4*>(g_tail_num + (long long)g * HD + lane * 4) = num;
                if (lane == 0) g_tail_d[g] = d;
            }
            i = j;
        }
    }
    if (lane == 0) { g_head_seg[g] = hseg; g_tail_seg[g] = tseg; }
}

// K2: one CTA (128 threads) per segment. Reads precomputed bounds (no binary
// search), scans the few warps overlapping the segment for head/tail partials;
// if none match, the segment was exclusive and lives in g_num_acc/g_d_acc.
// Empty segment: g_seg_end[s] == 0 (never written; zero-init) -> output 0.
__global__ void __launch_bounds__(HD)
gap_k2(float* __restrict__ out, int N)
{
    const int s = blockIdx.x;
    const int t = threadIdx.x;

    const int se = g_seg_end[s];
    if (se == 0) { out[(long long)s * HD + t] = 0.0f; return; }
    const int ss = g_seg_start[s];

    const int rpw = (N + NWTOT - 1) / NWTOT;
    const int glo = ss / rpw;
    const int ghi = (se - 1) / rpw;

    float num = 0.0f, d = 0.0f;
    int matches = 0;
    for (int g = glo; g <= ghi; g++) {
        if (g_head_seg[g] == s) { num += g_head_num[(long long)g * HD + t]; d += g_head_d[g]; matches++; }
        if (g_tail_seg[g] == s) { num += g_tail_num[(long long)g * HD + t]; d += g_tail_d[g]; matches++; }
    }
    if (matches == 0) {
        num = g_num_acc[(long long)s * HD + t];
        d   = g_d_acc[s];
    }
    out[(long long)s * HD + t] = num / (d + 1e-16f);
}

extern "C" void kernel_launch(void* const* d_in, const int* in_sizes, int n_in,
                              void* d_out, int out_size)
{
    const float* x     = (const float*)d_in[0];
    // d_in[1] = edge_index (unused by the forward math)
    const int*   batch = (const int*)d_in[2];
    const float* W     = (const float*)d_in[3];
    // d_in[4] = b (zeros; cancels in the softmax)
    float* out = (float*)d_out;

    const int N = in_sizes[2];
    const int B = out_size / HD;

    gap_k1<<<GRID1, NTHREADS>>>(x, batch, W, N);
    gap_k2<<<B, HD>>>(out, N);
}

// round 10
// speedup vs baseline: 1.0595x; 1.0139x over previous
#include <cuda_runtime.h>
#include <cuda_bf16.h>
#include <cstdint>

#define HD 128
#define WPB 8                       // warps per CTA
#define NTHREADS (WPB * 32)
#define GRID1 740                   // 148 SMs * 5 CTAs (regs=48 -> 5 CTAs/SM resident)
#define NWTOT (GRID1 * WPB)         // 5920 worker warps
#define BMAX 2048                   // scratch sized for up to 2048 segments

// ---- persistent scratch (zero-initialized at module load) ----
// Invariant: for an EMPTY segment s nothing ever writes g_seg_end[s] (any run,
// any replay) so it stays 0; a NON-EMPTY segment gets g_seg_end[s]=j>=1 from
// exactly one warp. Hence g_seg_end[s]==0 <=> empty; no init kernel needed.
__device__ float g_head_num[NWTOT * HD];
__device__ float g_tail_num[NWTOT * HD];
__device__ float g_head_d[NWTOT];
__device__ float g_tail_d[NWTOT];
__device__ int   g_head_seg[NWTOT];
__device__ int   g_tail_seg[NWTOT];
__device__ float g_num_acc[BMAX * HD];   // direct-stored exclusive segments
__device__ float g_d_acc[BMAX];
__device__ int   g_seg_start[BMAX];
__device__ int   g_seg_end[BMAX];        // 0 => empty segment

// K1: each global warp g owns contiguous rows [g*RPW, min((g+1)*RPW, N)).
// Splits its range into same-segment runs; accumulates d = sum exp(s_i),
// num = sum exp(s_i)*x_i per run; flushes each run to either the exclusive
// per-segment slot or the warp's head/tail partial slot. Records the TRUE
// segment start/end rows (single writer each) so K2 needs no search.
__global__ void __launch_bounds__(NTHREADS, 5)
gap_k1(const float* __restrict__ x,
       const int*   __restrict__ batch,
       const float* __restrict__ W,
       int N)
{
    const int wid  = threadIdx.x >> 5;
    const int lane = threadIdx.x & 31;
    const int g    = blockIdx.x * WPB + wid;

    const int rpw = (N + NWTOT - 1) / NWTOT;
    const long long rl = (long long)g * rpw;

    int hseg = -1, tseg = -1;

    if (rl < N) {
        const int lo = (int)rl;
        const int hi = min(lo + rpw, N);
        const float4 Wv = *reinterpret_cast<const float4*>(W + lane * 4);
        const long long col = (long long)lane * 4;

        int i = lo;
        while (i < hi) {
            const int seg = batch[i];
            // upper_bound(seg) in (i, hi)
            int a = i + 1, b = hi;
            while (a < b) { int m = (a + b) >> 1; if (batch[m] <= seg) a = m + 1; else b = m; }
            const int j = a;

            float  d = 0.0f;
            float4 num = make_float4(0.0f, 0.0f, 0.0f, 0.0f);

            int r = i;
            // 4 consecutive rows per iter: 4 independent LDG.128, 2KB contiguous
            for (; r + 4 <= j; r += 4) {
                const float4 x0 = __ldcs(reinterpret_cast<const float4*>(x + (long long)(r    ) * HD + col));
                const float4 x1 = __ldcs(reinterpret_cast<const float4*>(x + (long long)(r + 1) * HD + col));
                const float4 x2 = __ldcs(reinterpret_cast<const float4*>(x + (long long)(r + 2) * HD + col));
                const float4 x3 = __ldcs(reinterpret_cast<const float4*>(x + (long long)(r + 3) * HD + col));

                float p0 = x0.x * Wv.x + x0.y * Wv.y + x0.z * Wv.z + x0.w * Wv.w;
                float p1 = x1.x * Wv.x + x1.y * Wv.y + x1.z * Wv.z + x1.w * Wv.w;
                float p2 = x2.x * Wv.x + x2.y * Wv.y + x2.z * Wv.z + x2.w * Wv.w;
                float p3 = x3.x * Wv.x + x3.y * Wv.y + x3.z * Wv.z + x3.w * Wv.w;
                #pragma unroll
                for (int o = 16; o > 0; o >>= 1) {
                    p0 += __shfl_xor_sync(0xffffffffu, p0, o);
                    p1 += __shfl_xor_sync(0xffffffffu, p1, o);
                    p2 += __shfl_xor_sync(0xffffffffu, p2, o);
                    p3 += __shfl_xor_sync(0xffffffffu, p3, o);
                }
                const float e0 = __expf(p0);
                const float e1 = __expf(p1);
                const float e2 = __expf(p2);
                const float e3 = __expf(p3);
                d += (e0 + e1) + (e2 + e3);
                num.x += e0 * x0.x + e1 * x1.x + e2 * x2.x + e3 * x3.x;
                num.y += e0 * x0.y + e1 * x1.y + e2 * x2.y + e3 * x3.y;
                num.z += e0 * x0.z + e1 * x1.z + e2 * x2.z + e3 * x3.z;
                num.w += e0 * x0.w + e1 * x1.w + e2 * x2.w + e3 * x3.w;
            }
            for (; r < j; r++) {
                const float4 xv = __ldcs(reinterpret_cast<const float4*>(x + (long long)r * HD + col));
                float p = xv.x * Wv.x + xv.y * Wv.y + xv.z * Wv.z + xv.w * Wv.w;
                #pragma unroll
                for (int o = 16; o > 0; o >>= 1) p += __shfl_xor_sync(0xffffffffu, p, o);
                const float e = __expf(p);
                d += e;
                num.x += e * xv.x; num.y += e * xv.y; num.z += e * xv.z; num.w += e * xv.w;
            }

            const bool sb = (i == lo) && (lo > 0) && (batch[lo - 1] == seg);   // continues before
            const bool ea = (j == hi) && (hi < N) && (batch[hi] == seg);       // continues after

            if (lane == 0) {
                if (!sb) g_seg_start[seg] = i;   // true segment start (unique writer)
                if (!ea) g_seg_end[seg]   = j;   // true segment end   (unique writer, j >= 1)
            }

            if (!sb && !ea) {
                // exclusive segment: this warp is the sole contributor
                *reinterpret_cast<float4*>(g_num_acc + (long long)seg * HD + lane * 4) = num;
                if (lane == 0) g_d_acc[seg] = d;
            } else if (sb) {
                hseg = seg;
                *reinterpret_cast<float4*>(g_head_num + (long long)g * HD + lane * 4) = num;
                if (lane == 0) g_head_d[g] = d;
            } else {
                tseg = seg;
                *reinterpret_cast<float4*>(g_tail_num + (long long)g * HD + lane * 4) = num;
                if (lane == 0) g_tail_d[g] = d;
            }
            i = j;
        }
    }
    if (lane == 0) { g_head_seg[g] = hseg; g_tail_seg[g] = tseg; }
}

// K2: one WARP per segment (8 segments per 256-thread CTA, grid B/8).
// Lane l owns columns [4l, 4l+4) as a float4. The head/tail scan conditions
// are lane-uniform (seg ids are scalar per scratch row) so there is no
// divergence; scratch rows are 512B and each lane's float4 load is coalesced.
// Empty segment: g_seg_end[s] == 0 (never written; zero-init) -> zeros.
__global__ void __launch_bounds__(NTHREADS)
gap_k2(float* __restrict__ out, int N, int B)
{
    const int wid  = threadIdx.x >> 5;
    const int lane = threadIdx.x & 31;
    const int s    = blockIdx.x * WPB + wid;
    if (s >= B) return;

    float4* outv = reinterpret_cast<float4*>(out + (long long)s * HD + lane * 4);

    const int se = g_seg_end[s];
    if (se == 0) { *outv = make_float4(0.0f, 0.0f, 0.0f, 0.0f); return; }
    const int ss = g_seg_start[s];

    const int rpw = (N + NWTOT - 1) / NWTOT;
    const int glo = ss / rpw;
    const int ghi = (se - 1) / rpw;

    float4 num = make_float4(0.0f, 0.0f, 0.0f, 0.0f);
    float  d = 0.0f;
    int matches = 0;
    for (int g = glo; g <= ghi; g++) {
        if (g_head_seg[g] == s) {
            const float4 v = *reinterpret_cast<const float4*>(g_head_num + (long long)g * HD + lane * 4);
            num.x += v.x; num.y += v.y; num.z += v.z; num.w += v.w;
            d += g_head_d[g]; matches++;
        }
        if (g_tail_seg[g] == s) {
            const float4 v = *reinterpret_cast<const float4*>(g_tail_num + (long long)g * HD + lane * 4);
            num.x += v.x; num.y += v.y; num.z += v.z; num.w += v.w;
            d += g_tail_d[g]; matches++;
        }
    }
    if (matches == 0) {
        num = *reinterpret_cast<const float4*>(g_num_acc + (long long)s * HD + lane * 4);
        d   = g_d_acc[s];
    }
    const float inv = 1.0f / (d + 1e-16f);
    num.x *= inv; num.y *= inv; num.z *= inv; num.w *= inv;
    *outv = num;
}

extern "C" void kernel_launch(void* const* d_in, const int* in_sizes, int n_in,
                              void* d_out, int out_size)
{
    const float* x     = (const float*)d_in[0];
    // d_in[1] = edge_index (unused by the forward math)
    const int*   batch = (const int*)d_in[2];
    const float* W     = (const float*)d_in[3];
    // d_in[4] = b (zeros; cancels in the softmax)
    float* out = (float*)d_out;

    const int N = in_sizes[2];
    const int B = out_size / HD;

    gap_k1<<<GRID1, NTHREADS>>>(x, batch, W, N);
    gap_k2<<<(B + WPB - 1) / WPB, NTHREADS>>>(out, N, B);
}